// round 14
// baseline (speedup 1.0000x reference)
#include <cuda_runtime.h>

// Problem constants
#define TSEQ 1024
#define NB   32      // batch
#define ID   512     // input dim
#define HD   512     // hidden dim
#define GD   2048    // 4*H gate rows
#define NBLK_DIR 64  // persistent blocks per direction (8 hidden units each)
#define REC_THREADS 256

typedef unsigned long long ull;

// Scratch (device globals: no runtime allocation allowed)
__device__ float g_xw[(size_t)TSEQ * GD * NB];   // [t][g][b], 256MB
__device__ float g_hbuf[2][2][HD * NB];          // [dir][ping][u*32 + b]
__device__ unsigned g_barcnt[2];   // flat barrier arrival counters (monotonic)

// ---------------------------------------------------------------------------
// packed fp32x2 ops (Blackwell)
// ---------------------------------------------------------------------------
__device__ __forceinline__ void ffma2(ull& d, ull a, ull b) {
    asm("fma.rn.f32x2 %0, %1, %2, %0;" : "+l"(d) : "l"(a), "l"(b));
}
__device__ __forceinline__ ull addf2(ull a, ull b) {
    ull r;
    asm("add.rn.f32x2 %0, %1, %2;" : "=l"(r) : "l"(a), "l"(b));
    return r;
}
__device__ __forceinline__ ull dup2(float x) {
    ull r;
    asm("mov.b64 %0, {%1, %1};" : "=l"(r) : "f"(x));
    return r;
}
__device__ __forceinline__ float pairsum(ull v) {
    float2 f = *reinterpret_cast<float2*>(&v);
    return f.x + f.y;
}

__device__ __forceinline__ unsigned ld_acquire(const unsigned* p) {
    unsigned v;
    asm volatile("ld.acquire.gpu.u32 %0, [%1];" : "=r"(v) : "l"(p) : "memory");
    return v;
}

__device__ __forceinline__ float sigf(float x) {
    return __fdividef(1.f, 1.f + __expf(-x));
}
__device__ __forceinline__ float tanhfast(float x) {
    return __fdividef(2.f, 1.f + __expf(-2.f * x)) - 1.f;
}

// ---------------------------------------------------------------------------
// Flat per-direction barrier, counter-only (R13-proven):
//   arrive: red.release (no return -> arriver never waits on L2 round trip)
//   wait:   ld.acquire poll on the same counter (tid0 only + __syncthreads)
// ---------------------------------------------------------------------------
__device__ __forceinline__ void bar_arrive_red(int dir) {
    asm volatile("red.release.gpu.global.add.u32 [%0], %1;"
                 :: "l"(&g_barcnt[dir]), "r"(1u) : "memory");
}
__device__ __forceinline__ void bar_wait_cnt(int dir, unsigned target) {
    while ((int)(ld_acquire(&g_barcnt[dir]) - target) < 0) { }
}

// ---------------------------------------------------------------------------
// xw[t][g][b] = sum_i x[t][b][i] * W_ih[g][i] + (b_ih[g] + b_hh[g])
// Also zeroes its 2KB slice of d_out.  (unchanged from R13)
// ---------------------------------------------------------------------------
__global__ __launch_bounds__(256) void xw_gemm(
    const float* __restrict__ x,
    const float* __restrict__ Wih,
    const float* __restrict__ bih,
    const float* __restrict__ bhh,
    float4* __restrict__ out4)
{
    __shared__ float xs[NB * 34];   // [b][kk], stride 34
    __shared__ float ws[64 * 32];   // [g_local][kk]

    if (threadIdx.x < 128)
        out4[(size_t)blockIdx.x * 128 + threadIdx.x] = make_float4(0.f, 0.f, 0.f, 0.f);

    int t   = blockIdx.x >> 5;
    int g0  = (blockIdx.x & 31) << 6;
    int tid = threadIdx.x;
    int gg  = tid >> 5;
    int b   = tid & 31;

    ull acc[8];
#pragma unroll
    for (int j = 0; j < 8; j++) acc[j] = 0ull;

    const float* xt = x + (size_t)t * NB * ID;

    for (int k0 = 0; k0 < ID; k0 += 32) {
#pragma unroll
        for (int r = 0; r < 4; r++) {
            int bl = (tid >> 5) + (r << 3);
            int kk = tid & 31;
            xs[bl * 34 + kk] = xt[bl * ID + k0 + kk];
        }
#pragma unroll
        for (int r = 0; r < 8; r++) {
            int gl = (tid >> 5) + (r << 3);
            int kk = tid & 31;
            ws[gl * 32 + kk] = Wih[(size_t)(g0 + gl) * ID + k0 + kk];
        }
        __syncthreads();

#pragma unroll
        for (int kk = 0; kk < 32; kk += 4) {
            const ull* xu = (const ull*)&xs[b * 34 + kk];
            ull x01 = xu[0];
            ull x23 = xu[1];
#pragma unroll
            for (int j = 0; j < 8; j++) {
                ulonglong2 wv = *(const ulonglong2*)&ws[(gg * 8 + j) * 32 + kk];
                ffma2(acc[j], x01, wv.x);
                ffma2(acc[j], x23, wv.y);
            }
        }
        __syncthreads();
    }

    float* outp = g_xw + (size_t)t * GD * NB;
#pragma unroll
    for (int j = 0; j < 8; j++) {
        int g = g0 + gg * 8 + j;
        outp[g * NB + b] = pairsum(acc[j]) + bih[g] + bhh[g];
    }
}

// ---------------------------------------------------------------------------
// Persistent bidirectional zoneout-LSTM recurrence.
// 128 blocks: 0..63 fwd, 64..127 bwd. Block: 8 hidden units (32 gate rows) x 32 b.
// R14 GEMV: warp w owns k in [64w, 64w+64). lane = (rgr = lane&15 -> rows
// 2rgr, 2rgr+1; kg = lane>>4 -> 32-k half). Per k: 1 LDS.64 (own W pair from
// per-lane-sliced Wp) + 8 LDS.128 h (16-lane broadcast dedups -> 1 wf each)
// + 32 FFMA2. W smem traffic per step: 64 wf/warp (was 2048).
// h smem layout per warp region: [i:32][kg stride 36][b:32] (bank-verified).
// Fold: single shfl_xor(16) round, static register indices only.
// ---------------------------------------------------------------------------
__global__ __launch_bounds__(REC_THREADS, 1) void lstm_rec(
    const float* __restrict__ Whh, float* __restrict__ out)
{
    extern __shared__ float smem[];
    ull*   Wp   = (ull*)smem;                    // 16384 floats: ull[w*1024 + i*32 + lane]
    float* Hs   = smem + 16384;                  // 18432 floats: w*2304 + i*72 + kg*36 + b
    float* gbuf = smem + 16384 + 18432;          // 8704 floats:  gbuf[w*1088 + row*34 + b]

    int bid  = blockIdx.x;
    int dir  = bid >> 6;
    int j0   = (bid & 63) << 3;
    int tid  = threadIdx.x;
    int w    = tid >> 5;
    int lane = tid & 31;
    int rgr  = lane & 15;       // rows 2rgr, 2rgr+1
    int kg   = lane >> 4;       // k half within warp slice
    int u_l  = w;               // cell phase: unit-local 0..7
    int gu   = j0 + u_l;

    // One-time: load this lane's W slice into Wp (per-lane sliced, 2 rows x 32 k).
    // local row lr -> global W row (lr>>3)*512 + j0 + (lr&7)
    {
        int lr0 = 2 * rgr, lr1 = lr0 + 1;
        int ga  = ((lr0 >> 3) << 9) + j0 + (lr0 & 7);
        int gb  = ((lr1 >> 3) << 9) + j0 + (lr1 & 7);
        const float* p0 = Whh + (size_t)ga * HD;
        const float* p1 = Whh + (size_t)gb * HD;
        int kb = (w << 6) + (kg << 5);
#pragma unroll 4
        for (int i = 0; i < 32; i++) {
            float2 f2 = make_float2(p0[kb + i], p1[kb + i]);
            *(float2*)&Wp[w * 1024 + i * 32 + lane] = f2;
        }
    }

    // init h(step 0) = 0 (own units); c and h_old live in registers
    float c_reg = 0.f;
    float h_reg = 0.f;
    g_hbuf[dir][0][gu * 32 + lane] = 0.f;

    // barrier base for this launch (monotonic counter, replay-safe)
    unsigned base = ld_acquire(&g_barcnt[dir]) & ~(unsigned)(NBLK_DIR - 1);

    __syncthreads();
    if (tid == 0) bar_arrive_red(dir);     // publish h0

    const ull*   wp_w = Wp + (w << 10) + lane;
    const float* hb   = Hs + w * 2304 + kg * 36;

    for (int s = 0; s < TSEQ; s++) {
        int t = dir ? (TSEQ - 1 - s) : s;
        const float* xw_t = g_xw + (size_t)t * GD * NB;

        // prefetch xw BEFORE the wait: DRAM latency hidden under the spin
        float xg0 = xw_t[(0 * HD + gu) * NB + lane];
        float xg1 = xw_t[(1 * HD + gu) * NB + lane];
        float xg2 = xw_t[(2 * HD + gu) * NB + lane];
        float xg3 = xw_t[(3 * HD + gu) * NB + lane];

        // wait: all 64 blocks of this direction have published h_s
        if (tid == 0) bar_wait_cnt(dir, base + (unsigned)NBLK_DIR * (s + 1));
        __syncthreads();

        // per-warp copy of its own h k-range [64w, 64w+64) into region layout
        {
            const float4* hsrc = (const float4*)g_hbuf[dir][s & 1];
            float4* Hs4 = (float4*)Hs;
#pragma unroll
            for (int it = 0; it < 16; it++) {
                int e  = (it << 5) + lane;   // 0..511 float4 units of this slice
                int kl = e >> 3;             // local k 0..63
                int b4 = e & 7;
                float4 v = __ldcg(&hsrc[(w << 9) + e]);
                Hs4[w * 576 + (kl & 31) * 18 + (kl >> 5) * 9 + b4] = v;
            }
            __syncwarp();   // order cross-lane STS -> LDS within this warp
        }

        // GEMV: 2 rows x 16 batch-pairs per lane over 32 k
        ull acc[2][16];
#pragma unroll
        for (int p = 0; p < 16; p++) { acc[0][p] = 0ull; acc[1][p] = 0ull; }

#pragma unroll 4
        for (int i = 0; i < 32; i++) {
            float2 wv = *(const float2*)(wp_w + (i << 5));
            ull wd0 = dup2(wv.x);
            ull wd1 = dup2(wv.y);
            const float* hp = hb + i * 72;
#pragma unroll
            for (int j = 0; j < 8; j++) {
                ulonglong2 hh = *(const ulonglong2*)(hp + (j << 2));
                ffma2(acc[0][2 * j],     wd0, hh.x);
                ffma2(acc[0][2 * j + 1], wd0, hh.y);
                ffma2(acc[1][2 * j],     wd1, hh.x);
                ffma2(acc[1][2 * j + 1], wd1, hh.y);
            }
        }

        // single-round k-fold (xor 16) + store: STATIC register indices only.
        // kg=0 lane keeps bp [0,8), kg=1 keeps [8,16); final bp = 8*kg + q.
        {
            bool kB = (lane & 16) != 0;
            float* gp0 = gbuf + w * 1088 + (kg << 4);   // 2*(8*kg)
#pragma unroll
            for (int r = 0; r < 2; r++) {
                float* gr = gp0 + (2 * rgr + r) * 34;
#pragma unroll
                for (int q = 0; q < 8; q++) {
                    ull snd = kB ? acc[r][q] : acc[r][q + 8];
                    ull rcv = __shfl_xor_sync(0xFFFFFFFFu, snd, 16);
                    ull fin = addf2(kB ? acc[r][q + 8] : acc[r][q], rcv);
                    *(ull*)(gr + 2 * q) = fin;
                }
            }
        }
        __syncthreads();

        // cell update: thread = (unit u_l = w, batch lane); 8 partial sets per gate
        {
            int b = lane;
            float iv = xg0, fv = xg1, gv = xg2, ov = xg3;
#pragma unroll
            for (int sw = 0; sw < 8; sw++) {
                const float* gp = gbuf + sw * 1088 + b;
                iv += gp[(0 * 8 + u_l) * 34];
                fv += gp[(1 * 8 + u_l) * 34];
                gv += gp[(2 * 8 + u_l) * 34];
                ov += gp[(3 * 8 + u_l) * 34];
            }
            iv = sigf(iv);
            fv = sigf(fv);
            gv = tanhfast(gv);
            ov = sigf(ov);
            float c_new = fv * c_reg + iv * gv;
            float h_new = ov * tanhfast(c_new);
            c_reg = 0.9f * c_new + 0.1f * c_reg;
            float h_bl = 0.9f * h_new + 0.1f * h_reg;
            h_reg = h_bl;
            g_hbuf[dir][(s + 1) & 1][gu * 32 + lane] = h_bl;
            // fire-and-forget global add; exactly two commutative fp32 adds
            // per output element -> deterministic
            atomicAdd(&out[(size_t)t * (NB * HD) + lane * HD + gu], h_bl);
        }

        // publish h_{s+1}
        __syncthreads();
        if (tid == 0) bar_arrive_red(dir);
    }
}

// ---------------------------------------------------------------------------
extern "C" void kernel_launch(void* const* d_in, const int* in_sizes, int n_in,
                              void* d_out, int out_size) {
    const float* x   = (const float*)d_in[0];
    const float* Wih = (const float*)d_in[1];
    const float* Whh = (const float*)d_in[2];
    const float* bih = (const float*)d_in[3];
    const float* bhh = (const float*)d_in[4];
    float* out = (float*)d_out;

    const int rec_smem = (16384 + 18432 + 8704) * (int)sizeof(float); // 174080 B
    cudaFuncSetAttribute(lstm_rec, cudaFuncAttributeMaxDynamicSharedMemorySize, rec_smem);

    xw_gemm<<<TSEQ * 32, 256>>>(x, Wih, bih, bhh, (float4*)out);
    lstm_rec<<<2 * NBLK_DIR, REC_THREADS, rec_smem>>>(Whh, out);
}

// round 15
// speedup vs baseline: 1.1236x; 1.1236x over previous
#include <cuda_runtime.h>

// Problem constants
#define TSEQ 1024
#define NB   32      // batch
#define ID   512     // input dim
#define HD   512     // hidden dim
#define GD   2048    // 4*H gate rows
#define NBLK_DIR 64  // persistent blocks per direction (8 hidden units each)
#define REC_THREADS 256

typedef unsigned long long ull;

// Scratch (device globals: no runtime allocation allowed)
__device__ float g_xw[(size_t)TSEQ * GD * NB];   // [t][g][b], 256MB
__device__ float g_hbuf[2][2][HD * NB];          // [dir][ping][u*32 + b]
__device__ unsigned g_barcnt[2];   // flat barrier arrival counters (monotonic)

// ---------------------------------------------------------------------------
// packed fp32x2 ops (Blackwell)
// ---------------------------------------------------------------------------
__device__ __forceinline__ void ffma2(ull& d, ull a, ull b) {
    asm("fma.rn.f32x2 %0, %1, %2, %0;" : "+l"(d) : "l"(a), "l"(b));
}
__device__ __forceinline__ ull addf2(ull a, ull b) {
    ull r;
    asm("add.rn.f32x2 %0, %1, %2;" : "=l"(r) : "l"(a), "l"(b));
    return r;
}
__device__ __forceinline__ ull dup2(float x) {
    ull r;
    asm("mov.b64 %0, {%1, %1};" : "=l"(r) : "f"(x));
    return r;
}
__device__ __forceinline__ float pairsum(ull v) {
    float2 f = *reinterpret_cast<float2*>(&v);
    return f.x + f.y;
}

__device__ __forceinline__ unsigned ld_acquire(const unsigned* p) {
    unsigned v;
    asm volatile("ld.acquire.gpu.u32 %0, [%1];" : "=r"(v) : "l"(p) : "memory");
    return v;
}

__device__ __forceinline__ float sigf(float x) {
    return __fdividef(1.f, 1.f + __expf(-x));
}
__device__ __forceinline__ float tanhfast(float x) {
    return __fdividef(2.f, 1.f + __expf(-2.f * x)) - 1.f;
}

// ---------------------------------------------------------------------------
// Flat per-direction barrier, counter-only (R13-proven)
// ---------------------------------------------------------------------------
__device__ __forceinline__ void bar_arrive_red(int dir) {
    asm volatile("red.release.gpu.global.add.u32 [%0], %1;"
                 :: "l"(&g_barcnt[dir]), "r"(1u) : "memory");
}
__device__ __forceinline__ void bar_wait_cnt(int dir, unsigned target) {
    while ((int)(ld_acquire(&g_barcnt[dir]) - target) < 0) { }
}

// ---------------------------------------------------------------------------
// xw v2: register-tiled GEMM. Block = (t, 64-gate group), 256 threads.
// Warp w -> gates 8w..8w+7 (local), all 32 batches. lane = (ks = lane>>3
// [4-way k split], bq = lane&7 [batches 4bq..4bq+3 = 2 bp]).
// k chunks of 32 staged k-major in smem (ws stride 66, xs stride 36).
// acc[8 gates][2 bp] accumulates across ALL chunks; single 2-round
// shfl_xor k-fold at the end (static value-selects), direct STG. No gbuf.
// ---------------------------------------------------------------------------
__global__ void __launch_bounds__(256, 3) xw_gemm(
    const float* __restrict__ x,
    const float* __restrict__ Wih,
    const float* __restrict__ bih,
    const float* __restrict__ bhh,
    float4* __restrict__ out4)
{
    __shared__ float ws[32 * 66];   // [kk][g], stride 66
    __shared__ float xs[32 * 36];   // [kk][b], stride 36

    int t   = blockIdx.x >> 5;
    int g0  = (blockIdx.x & 31) << 6;
    int tid = threadIdx.x;
    int w   = tid >> 5;
    int lane = tid & 31;
    int ks  = lane >> 3;
    int bq  = lane & 7;

    // zero this block's 2KB slice of d_out (atomicAdd target for the recurrence)
    if (tid < 128)
        out4[(size_t)blockIdx.x * 128 + tid] = make_float4(0.f, 0.f, 0.f, 0.f);

    // final gate subset of this lane after the fold: gb = 4*(ks&1) + 2*(ks>>1)
    int gb = ((ks & 1) << 2) | (ks & 2);
    float bias0 = bih[g0 + 8 * w + gb]     + bhh[g0 + 8 * w + gb];
    float bias1 = bih[g0 + 8 * w + gb + 1] + bhh[g0 + 8 * w + gb + 1];

    ull acc[8][2];
#pragma unroll
    for (int i = 0; i < 8; i++) { acc[i][0] = 0ull; acc[i][1] = 0ull; }

    const float* xt = x + (size_t)t * NB * ID;

    // load-index precomputes
    int gl = tid >> 2, mq = tid & 3;      // W loader: row gl, 8-k group mq
    int bl = tid >> 3, mm = tid & 7;      // x loader: row bl, 4-k group mm

    for (int kc = 0; kc < ID; kc += 32) {
        __syncthreads();   // previous GEMV reads done before overwrite
        // W chunk -> ws[kk][g] (k-major)
        {
            const float4* src = (const float4*)(Wih + (size_t)(g0 + gl) * ID + kc + 8 * mq);
            float4 a = src[0], b = src[1];
            float* wp = ws + gl;
            wp[(8 * mq + 0) * 66] = a.x;
            wp[(8 * mq + 1) * 66] = a.y;
            wp[(8 * mq + 2) * 66] = a.z;
            wp[(8 * mq + 3) * 66] = a.w;
            wp[(8 * mq + 4) * 66] = b.x;
            wp[(8 * mq + 5) * 66] = b.y;
            wp[(8 * mq + 6) * 66] = b.z;
            wp[(8 * mq + 7) * 66] = b.w;
        }
        // x chunk -> xs[kk][b] (k-major)
        {
            float4 v = *(const float4*)(xt + bl * ID + kc + 4 * mm);
            float* xp = xs + bl;
            xp[(4 * mm + 0) * 36] = v.x;
            xp[(4 * mm + 1) * 36] = v.y;
            xp[(4 * mm + 2) * 36] = v.z;
            xp[(4 * mm + 3) * 36] = v.w;
        }
        __syncthreads();

        // GEMV: 8 iters, k = 4*it + ks per lane
#pragma unroll
        for (int it = 0; it < 8; it++) {
            int kk = (it << 2) | ks;
            const float* wrow = ws + kk * 66 + 8 * w;
            float2 w01 = *(const float2*)(wrow);       // uniform within ks group
            float2 w23 = *(const float2*)(wrow + 2);
            float2 w45 = *(const float2*)(wrow + 4);
            float2 w67 = *(const float2*)(wrow + 6);
            ulonglong2 xv = *(const ulonglong2*)(xs + kk * 36 + 4 * bq);
            ull wd;
            wd = dup2(w01.x); ffma2(acc[0][0], wd, xv.x); ffma2(acc[0][1], wd, xv.y);
            wd = dup2(w01.y); ffma2(acc[1][0], wd, xv.x); ffma2(acc[1][1], wd, xv.y);
            wd = dup2(w23.x); ffma2(acc[2][0], wd, xv.x); ffma2(acc[2][1], wd, xv.y);
            wd = dup2(w23.y); ffma2(acc[3][0], wd, xv.x); ffma2(acc[3][1], wd, xv.y);
            wd = dup2(w45.x); ffma2(acc[4][0], wd, xv.x); ffma2(acc[4][1], wd, xv.y);
            wd = dup2(w45.y); ffma2(acc[5][0], wd, xv.x); ffma2(acc[5][1], wd, xv.y);
            wd = dup2(w67.x); ffma2(acc[6][0], wd, xv.x); ffma2(acc[6][1], wd, xv.y);
            wd = dup2(w67.y); ffma2(acc[7][0], wd, xv.x); ffma2(acc[7][1], wd, xv.y);
        }
    }

    // 2-round k-fold across the 4 ks groups (STATIC register indices only).
    bool kA = (lane & 8) != 0;    // ks bit 0
    bool kB = (lane & 16) != 0;   // ks bit 1
    ull kept[4][2];
#pragma unroll
    for (int j = 0; j < 4; j++)
#pragma unroll
        for (int p = 0; p < 2; p++) {
            ull snd = kA ? acc[j][p] : acc[j + 4][p];
            ull rcv = __shfl_xor_sync(0xFFFFFFFFu, snd, 8);
            kept[j][p] = addf2(kA ? acc[j + 4][p] : acc[j][p], rcv);
        }
    ull fin[2][2];
#pragma unroll
    for (int j = 0; j < 2; j++)
#pragma unroll
        for (int p = 0; p < 2; p++) {
            ull snd = kB ? kept[j][p] : kept[j + 2][p];
            ull rcv = __shfl_xor_sync(0xFFFFFFFFu, snd, 16);
            fin[j][p] = addf2(kB ? kept[j + 2][p] : kept[j][p], rcv);
        }

    // add bias (broadcast over the batch pair) and store
    {
        ull b0 = dup2(bias0), b1 = dup2(bias1);
        float* outp = g_xw + ((size_t)t * GD + g0 + 8 * w + gb) * NB + 4 * bq;
        *(ull*)(outp)           = addf2(fin[0][0], b0);
        *(ull*)(outp + 2)       = addf2(fin[0][1], b0);
        *(ull*)(outp + NB)      = addf2(fin[1][0], b1);
        *(ull*)(outp + NB + 2)  = addf2(fin[1][1], b1);
    }
}

// ---------------------------------------------------------------------------
// Persistent bidirectional zoneout-LSTM recurrence — R13 VERBATIM (best).
// ---------------------------------------------------------------------------
__global__ __launch_bounds__(REC_THREADS, 1) void lstm_rec(
    const float* __restrict__ Whh, float* __restrict__ out)
{
    extern __shared__ float smem[];
    float* Wt   = smem;             // 64KB: Wt[k*32 + row]
    float* Hs   = smem + 16384;     // 64KB: Hs[u*32 + b]
    float* gbuf = smem + 32768;     // 34KB: gbuf[w*1088 + row*34 + b]

    int bid  = blockIdx.x;
    int dir  = bid >> 6;
    int j0   = (bid & 63) << 3;
    int tid  = threadIdx.x;
    int w    = tid >> 5;
    int lane = tid & 31;
    int ks0  = lane >> 4;
    int rg   = (lane >> 2) & 3;
    int bg   = lane & 3;
    int u_l  = w;
    int gu   = j0 + u_l;

#pragma unroll 4
    for (int i = 0; i < 64; i++) {
        int idx = tid + (i << 8);
        int row = idx >> 9;
        int k   = idx & 511;
        int gr  = ((row >> 3) << 9) + j0 + (row & 7);
        Wt[k * 32 + row] = Whh[(size_t)gr * HD + k];
    }

    float c_reg = 0.f;
    float h_reg = 0.f;
    g_hbuf[dir][0][gu * 32 + lane] = 0.f;

    unsigned base = ld_acquire(&g_barcnt[dir]) & ~(unsigned)(NBLK_DIR - 1);

    __syncthreads();
    if (tid == 0) bar_arrive_red(dir);

    const float4* W4 = (const float4*)Wt;
    const float4* H4 = (const float4*)Hs;
    const int kbeg = (w << 6) + (ks0 << 5);

    for (int s = 0; s < TSEQ; s++) {
        int t = dir ? (TSEQ - 1 - s) : s;
        const float* xw_t = g_xw + (size_t)t * GD * NB;

        float xg0 = xw_t[(0 * HD + gu) * NB + lane];
        float xg1 = xw_t[(1 * HD + gu) * NB + lane];
        float xg2 = xw_t[(2 * HD + gu) * NB + lane];
        float xg3 = xw_t[(3 * HD + gu) * NB + lane];

        if (tid == 0) bar_wait_cnt(dir, base + (unsigned)NBLK_DIR * (s + 1));
        __syncthreads();

        {
            const float4* hsrc = (const float4*)g_hbuf[dir][s & 1];
            float4* hdst = (float4*)Hs;
#pragma unroll
            for (int i = 0; i < 16; i++) {
                int idx = (w << 9) + (i << 5) + lane;
                hdst[idx] = __ldcg(&hsrc[idx]);
            }
            __syncwarp();
        }

        ull acc[8][4];
#pragma unroll
        for (int i = 0; i < 8; i++)
#pragma unroll
            for (int j = 0; j < 4; j++) acc[i][j] = 0ull;

#pragma unroll 4
        for (int kk = 0; kk < 32; kk++) {
            int k = kbeg + kk;
            float4 wA = W4[(k << 3) + (rg << 1)];
            float4 wB = W4[(k << 3) + (rg << 1) + 1];
            ulonglong2 hA = *(const ulonglong2*)&H4[(k << 3) + (bg << 1)];
            ulonglong2 hB = *(const ulonglong2*)&H4[(k << 3) + (bg << 1) + 1];
            float wf[8] = {wA.x, wA.y, wA.z, wA.w, wB.x, wB.y, wB.z, wB.w};
#pragma unroll
            for (int i = 0; i < 8; i++) {
                ull wd = dup2(wf[i]);
                ffma2(acc[i][0], wd, hA.x);
                ffma2(acc[i][1], wd, hA.y);
                ffma2(acc[i][2], wd, hB.x);
                ffma2(acc[i][3], wd, hB.y);
            }
        }

        {
            float* gp0 = gbuf + w * 1088 + (bg << 3) + (ks0 << 2);
#pragma unroll
            for (int i = 0; i < 8; i++) {
                ull s0 = ks0 ? acc[i][0] : acc[i][2];
                ull s1 = ks0 ? acc[i][1] : acc[i][3];
                ull r0 = __shfl_xor_sync(0xFFFFFFFFu, s0, 16);
                ull r1 = __shfl_xor_sync(0xFFFFFFFFu, s1, 16);
                ull k0 = ks0 ? acc[i][2] : acc[i][0];
                ull k1 = ks0 ? acc[i][3] : acc[i][1];
                ull v0 = addf2(k0, r0);
                ull v1 = addf2(k1, r1);
                float* gp = gp0 + ((rg << 3) + i) * 34;
                *(ull*)gp = v0;
                *(ull*)(gp + 2) = v1;
            }
        }
        __syncthreads();

        {
            int b = lane;
            float iv = xg0, fv = xg1, gv = xg2, ov = xg3;
#pragma unroll
            for (int sw = 0; sw < 8; sw++) {
                const float* gp = gbuf + sw * 1088 + b;
                iv += gp[(0 * 8 + u_l) * 34];
                fv += gp[(1 * 8 + u_l) * 34];
                gv += gp[(2 * 8 + u_l) * 34];
                ov += gp[(3 * 8 + u_l) * 34];
            }
            iv = sigf(iv);
            fv = sigf(fv);
            gv = tanhfast(gv);
            ov = sigf(ov);
            float c_new = fv * c_reg + iv * gv;
            float h_new = ov * tanhfast(c_new);
            c_reg = 0.9f * c_new + 0.1f * c_reg;
            float h_bl = 0.9f * h_new + 0.1f * h_reg;
            h_reg = h_bl;
            g_hbuf[dir][(s + 1) & 1][gu * 32 + lane] = h_bl;
            // exactly two commutative fp32 adds per output element -> deterministic
            atomicAdd(&out[(size_t)t * (NB * HD) + lane * HD + gu], h_bl);
        }

        __syncthreads();
        if (tid == 0) bar_arrive_red(dir);
    }
}

// ---------------------------------------------------------------------------
extern "C" void kernel_launch(void* const* d_in, const int* in_sizes, int n_in,
                              void* d_out, int out_size) {
    const float* x   = (const float*)d_in[0];
    const float* Wih = (const float*)d_in[1];
    const float* Whh = (const float*)d_in[2];
    const float* bih = (const float*)d_in[3];
    const float* bhh = (const float*)d_in[4];
    float* out = (float*)d_out;

    const int rec_smem = (16384 + 16384 + 8 * 1088) * (int)sizeof(float); // 165888 B
    cudaFuncSetAttribute(lstm_rec, cudaFuncAttributeMaxDynamicSharedMemorySize, rec_smem);

    xw_gemm<<<TSEQ * 32, 256>>>(x, Wih, bih, bhh, (float4*)out);
    lstm_rec<<<2 * NBLK_DIR, REC_THREADS, rec_smem>>>(Whh, out);
}